// round 4
// baseline (speedup 1.0000x reference)
#include <cuda_runtime.h>
#include <cuda_bf16.h>
#include <cstddef>
#include <cstdint>

// Problem constants
#define BATCH 2
#define SEQ   2048
#define DIM   1024
#define NHEAD 16
#define HDIM  64
#define M_ROWS (BATCH * SEQ)   // 4096

// Scratch (device globals; no allocation allowed)
__device__ float g_q[(size_t)M_ROWS * DIM];        // 16 MB
__device__ float g_kv[(size_t)M_ROWS * 2 * DIM];   // 32 MB
__device__ float g_y[(size_t)M_ROWS * DIM];        // 16 MB

// ---------------------------------------------------------------------------
// 3xTF32 helpers
// ---------------------------------------------------------------------------
__device__ __forceinline__ void split_tf32(float x, uint32_t& hi, uint32_t& lo) {
    uint32_t h, l;
    asm("cvt.rna.tf32.f32 %0, %1;" : "=r"(h) : "f"(x));
    float r = x - __uint_as_float(h);
    asm("cvt.rna.tf32.f32 %0, %1;" : "=r"(l) : "f"(r));
    hi = h; lo = l;
}

__device__ __forceinline__ void mma8(float* c, const uint32_t* a, const uint32_t* b) {
    asm volatile(
        "mma.sync.aligned.m16n8k8.row.col.f32.tf32.tf32.f32 "
        "{%0,%1,%2,%3}, {%4,%5,%6,%7}, {%8,%9}, {%0,%1,%2,%3};"
        : "+f"(c[0]), "+f"(c[1]), "+f"(c[2]), "+f"(c[3])
        : "r"(a[0]), "r"(a[1]), "r"(a[2]), "r"(a[3]), "r"(b[0]), "r"(b[1]));
}

// ---------------------------------------------------------------------------
// Tensor-core GEMM: C[M,N] = A[M,K] @ B[K,N], fp32 in/out, 3xTF32 internally.
// Block tile 128x128, BK=16, 256 threads (8 warps, 2x4), warp tile 64x32.
// ---------------------------------------------------------------------------
__global__ __launch_bounds__(256) void gemm_tc(
    const float* __restrict__ A, const float* __restrict__ B,
    float* __restrict__ C, int M, int N, int K)
{
    __shared__ float As[16][132];  // [k][m], stride 132 -> conflict-free frag LDS
    __shared__ float Bs[16][132];  // [k][n]

    const int tid  = threadIdx.x;
    const int lane = tid & 31;
    const int warp = tid >> 5;
    const int warpM = warp >> 2;      // 0..1
    const int warpN = warp & 3;       // 0..3
    const int g  = lane >> 2;         // groupID 0..7
    const int qd = lane & 3;          // quad lane 0..3
    const int bRow = blockIdx.y * 128;
    const int bCol = blockIdx.x * 128;

    float acc[4][4][4];
#pragma unroll
    for (int i = 0; i < 4; i++)
#pragma unroll
        for (int j = 0; j < 4; j++)
#pragma unroll
            for (int r = 0; r < 4; r++) acc[i][j][r] = 0.0f;

    // Global load mapping (one float4 x2 per thread for each of A,B)
    const int aRow = tid >> 2;            // 0..63
    const int aCol = (tid & 3) * 4;       // 0,4,8,12
    const int bRowL = tid >> 5;           // 0..7
    const int bColL = (tid & 31) * 4;     // 0..124

    const float* Ap0 = A + (size_t)(bRow + aRow) * K + aCol;
    const float* Ap1 = A + (size_t)(bRow + aRow + 64) * K + aCol;
    const float* Bp0 = B + (size_t)bRowL * N + bCol + bColL;
    const float* Bp1 = B + (size_t)(bRowL + 8) * N + bCol + bColL;

    float4 ra0 = *(const float4*)Ap0;
    float4 ra1 = *(const float4*)Ap1;
    float4 rb0 = *(const float4*)Bp0;
    float4 rb1 = *(const float4*)Bp1;

    for (int k0 = 0; k0 < K; k0 += 16) {
        __syncthreads();
        As[aCol + 0][aRow] = ra0.x; As[aCol + 1][aRow] = ra0.y;
        As[aCol + 2][aRow] = ra0.z; As[aCol + 3][aRow] = ra0.w;
        As[aCol + 0][aRow + 64] = ra1.x; As[aCol + 1][aRow + 64] = ra1.y;
        As[aCol + 2][aRow + 64] = ra1.z; As[aCol + 3][aRow + 64] = ra1.w;
        *(float4*)&Bs[bRowL][bColL]     = rb0;
        *(float4*)&Bs[bRowL + 8][bColL] = rb1;
        __syncthreads();

        if (k0 + 16 < K) {   // prefetch next tile into registers
            ra0 = *(const float4*)(Ap0 + k0 + 16);
            ra1 = *(const float4*)(Ap1 + k0 + 16);
            rb0 = *(const float4*)(Bp0 + (size_t)(k0 + 16) * N);
            rb1 = *(const float4*)(Bp1 + (size_t)(k0 + 16) * N);
        }

#pragma unroll
        for (int ks = 0; ks < 2; ks++) {
            const int kb = ks * 8;
            uint32_t ahi[4][4], alo[4][4], bhi[4][2], blo[4][2];
#pragma unroll
            for (int mt = 0; mt < 4; mt++) {
                int r0 = warpM * 64 + mt * 16 + g;
                split_tf32(As[kb + qd][r0],         ahi[mt][0], alo[mt][0]);
                split_tf32(As[kb + qd][r0 + 8],     ahi[mt][1], alo[mt][1]);
                split_tf32(As[kb + qd + 4][r0],     ahi[mt][2], alo[mt][2]);
                split_tf32(As[kb + qd + 4][r0 + 8], ahi[mt][3], alo[mt][3]);
            }
#pragma unroll
            for (int nt = 0; nt < 4; nt++) {
                int c0 = warpN * 32 + nt * 8 + g;
                split_tf32(Bs[kb + qd][c0],     bhi[nt][0], blo[nt][0]);
                split_tf32(Bs[kb + qd + 4][c0], bhi[nt][1], blo[nt][1]);
            }
#pragma unroll
            for (int mt = 0; mt < 4; mt++)
#pragma unroll
                for (int nt = 0; nt < 4; nt++) {
                    mma8(acc[mt][nt], alo[mt], bhi[nt]);
                    mma8(acc[mt][nt], ahi[mt], blo[nt]);
                    mma8(acc[mt][nt], ahi[mt], bhi[nt]);
                }
        }
    }

#pragma unroll
    for (int mt = 0; mt < 4; mt++) {
        int r0 = bRow + warpM * 64 + mt * 16 + g;
#pragma unroll
        for (int nt = 0; nt < 4; nt++) {
            int c0 = bCol + warpN * 32 + nt * 8 + qd * 2;
            *(float2*)(C + (size_t)r0 * N + c0)       = make_float2(acc[mt][nt][0], acc[mt][nt][1]);
            *(float2*)(C + (size_t)(r0 + 8) * N + c0) = make_float2(acc[mt][nt][2], acc[mt][nt][3]);
        }
    }
}

// ---------------------------------------------------------------------------
// Flash attention with 3xTF32 mma for QK^T and PV.
// Grid: x = query block (64 rows each, 32 blocks), y = b*NHEAD + h (32).
// 128 threads (4 warps); each warp owns 16 query rows. KV tile = 64 keys.
// bufK doubles as Q staging, K tile, and P tile (after K is consumed).
// ---------------------------------------------------------------------------
__global__ __launch_bounds__(128) void attn_tc(
    const float* __restrict__ q, const float* __restrict__ kv,
    float* __restrict__ y)
{
    __shared__ float bufK[64][68];   // Q staging / K tile / P tile
    __shared__ float bufV[64][68];   // V tile

    const int tid  = threadIdx.x;
    const int lane = tid & 31;
    const int w    = tid >> 5;          // warp 0..3
    const int g  = lane >> 2;           // 0..7
    const int qd = lane & 3;            // 0..3
    const int qb = blockIdx.x;
    const int bh = blockIdx.y;
    const int b = bh >> 4, h = bh & 15;

    // ---- Stage Q (pre-scaled by 1/sqrt(64)) and extract fp32 fragments ----
    const float* qbase = q + ((size_t)(b * SEQ + qb * 64)) * DIM + h * HDIM;
    for (int i = tid; i < 64 * 16; i += 128) {
        int r = i >> 4, c4 = (i & 15) * 4;
        float4 v = *(const float4*)(qbase + (size_t)r * DIM + c4);
        bufK[r][c4 + 0] = v.x * 0.125f;
        bufK[r][c4 + 1] = v.y * 0.125f;
        bufK[r][c4 + 2] = v.z * 0.125f;
        bufK[r][c4 + 3] = v.w * 0.125f;
    }
    __syncthreads();

    float qf[8][4];                       // fp32 A-fragments (split on the fly)
    {
        int r0 = w * 16 + g;
#pragma unroll
        for (int kk = 0; kk < 8; kk++) {
            qf[kk][0] = bufK[r0][kk * 8 + qd];
            qf[kk][1] = bufK[r0 + 8][kk * 8 + qd];
            qf[kk][2] = bufK[r0][kk * 8 + qd + 4];
            qf[kk][3] = bufK[r0 + 8][kk * 8 + qd + 4];
        }
    }

    float o[8][4];
#pragma unroll
    for (int j = 0; j < 8; j++)
#pragma unroll
        for (int r = 0; r < 4; r++) o[j][r] = 0.0f;
    float m0 = -1e30f, m1 = -1e30f, l0 = 0.0f, l1 = 0.0f;

    const float* kbase = kv + (size_t)b * SEQ * (2 * DIM) + h * HDIM;
    const float* vbase = kbase + DIM;

    float (*Pw)[68] = (float(*)[68])&bufK[w * 16][0];  // warp-private 16-row P slice

    for (int kb0 = 0; kb0 < SEQ; kb0 += 64) {
        __syncthreads();   // bufK(Q frags or prev P) and bufV free for reuse
        for (int i = tid; i < 64 * 16; i += 128) {
            int r = i >> 4, c4 = (i & 15) * 4;
            size_t off = (size_t)(kb0 + r) * (2 * DIM) + c4;
            *(float4*)&bufK[r][c4] = *(const float4*)(kbase + off);
            *(float4*)&bufV[r][c4] = *(const float4*)(vbase + off);
        }
        __syncthreads();

        // ---- S = Q K^T (this warp's 16 rows x 64 keys) ----
        float s[8][4];
#pragma unroll
        for (int j = 0; j < 8; j++)
#pragma unroll
            for (int r = 0; r < 4; r++) s[j][r] = 0.0f;

#pragma unroll
        for (int kk = 0; kk < 8; kk++) {
            uint32_t ahi[4], alo[4];
            split_tf32(qf[kk][0], ahi[0], alo[0]);
            split_tf32(qf[kk][1], ahi[1], alo[1]);
            split_tf32(qf[kk][2], ahi[2], alo[2]);
            split_tf32(qf[kk][3], ahi[3], alo[3]);
#pragma unroll
            for (int j = 0; j < 8; j++) {
                uint32_t bhv[2], blv[2];
                split_tf32(bufK[j * 8 + g][kk * 8 + qd],     bhv[0], blv[0]);
                split_tf32(bufK[j * 8 + g][kk * 8 + qd + 4], bhv[1], blv[1]);
                mma8(s[j], alo, bhv);
                mma8(s[j], ahi, blv);
                mma8(s[j], ahi, bhv);
            }
        }

        // ---- Online softmax (registers + quad shuffles only) ----
        float rmax0 = -1e30f, rmax1 = -1e30f;
#pragma unroll
        for (int j = 0; j < 8; j++) {
            rmax0 = fmaxf(rmax0, fmaxf(s[j][0], s[j][1]));
            rmax1 = fmaxf(rmax1, fmaxf(s[j][2], s[j][3]));
        }
        rmax0 = fmaxf(rmax0, __shfl_xor_sync(0xffffffff, rmax0, 1));
        rmax0 = fmaxf(rmax0, __shfl_xor_sync(0xffffffff, rmax0, 2));
        rmax1 = fmaxf(rmax1, __shfl_xor_sync(0xffffffff, rmax1, 1));
        rmax1 = fmaxf(rmax1, __shfl_xor_sync(0xffffffff, rmax1, 2));

        float mn0 = fmaxf(m0, rmax0), mn1 = fmaxf(m1, rmax1);
        float f0 = __expf(m0 - mn0), f1 = __expf(m1 - mn1);
        float sum0 = 0.0f, sum1 = 0.0f;
#pragma unroll
        for (int j = 0; j < 8; j++) {
            s[j][0] = __expf(s[j][0] - mn0);
            s[j][1] = __expf(s[j][1] - mn0);
            s[j][2] = __expf(s[j][2] - mn1);
            s[j][3] = __expf(s[j][3] - mn1);
            sum0 += s[j][0] + s[j][1];
            sum1 += s[j][2] + s[j][3];
        }
        sum0 += __shfl_xor_sync(0xffffffff, sum0, 1);
        sum0 += __shfl_xor_sync(0xffffffff, sum0, 2);
        sum1 += __shfl_xor_sync(0xffffffff, sum1, 1);
        sum1 += __shfl_xor_sync(0xffffffff, sum1, 2);

        m0 = mn0; m1 = mn1;
        l0 = l0 * f0 + sum0;
        l1 = l1 * f1 + sum1;

#pragma unroll
        for (int j = 0; j < 8; j++) {
            o[j][0] *= f0; o[j][1] *= f0;
            o[j][2] *= f1; o[j][3] *= f1;
        }

        // ---- Relayout P: C-fragment -> A-fragment via warp-private smem ----
        __syncthreads();   // all warps done reading K tile
#pragma unroll
        for (int j = 0; j < 8; j++) {
            Pw[g][j * 8 + 2 * qd]         = s[j][0];
            Pw[g][j * 8 + 2 * qd + 1]     = s[j][1];
            Pw[g + 8][j * 8 + 2 * qd]     = s[j][2];
            Pw[g + 8][j * 8 + 2 * qd + 1] = s[j][3];
        }
        __syncwarp();

        // ---- O += P @ V ----
#pragma unroll
        for (int kk = 0; kk < 8; kk++) {
            uint32_t phi[4], plo[4];
            split_tf32(Pw[g][kk * 8 + qd],         phi[0], plo[0]);
            split_tf32(Pw[g + 8][kk * 8 + qd],     phi[1], plo[1]);
            split_tf32(Pw[g][kk * 8 + qd + 4],     phi[2], plo[2]);
            split_tf32(Pw[g + 8][kk * 8 + qd + 4], phi[3], plo[3]);
#pragma unroll
            for (int dt = 0; dt < 8; dt++) {
                uint32_t vh[2], vl[2];
                split_tf32(bufV[kk * 8 + qd][dt * 8 + g],     vh[0], vl[0]);
                split_tf32(bufV[kk * 8 + qd + 4][dt * 8 + g], vh[1], vl[1]);
                mma8(o[dt], plo, vh);
                mma8(o[dt], phi, vl);
                mma8(o[dt], phi, vh);
            }
        }
    }

    // ---- Epilogue: O /= l, write ----
    float inv0 = 1.0f / l0, inv1 = 1.0f / l1;
    float* ybase = y + ((size_t)(b * SEQ + qb * 64 + w * 16)) * DIM + h * HDIM;
#pragma unroll
    for (int dt = 0; dt < 8; dt++) {
        int c0 = dt * 8 + 2 * qd;
        *(float2*)(ybase + (size_t)g * DIM + c0) =
            make_float2(o[dt][0] * inv0, o[dt][1] * inv0);
        *(float2*)(ybase + (size_t)(g + 8) * DIM + c0) =
            make_float2(o[dt][2] * inv1, o[dt][3] * inv1);
    }
}

// ---------------------------------------------------------------------------
// Launch
// Inputs (metadata order): x [B,T,D], e [B,T,D], W_en [D,2D], W_q [D,D], W_o [D,D]
// Output: [B,T,D] fp32
// ---------------------------------------------------------------------------
extern "C" void kernel_launch(void* const* d_in, const int* in_sizes, int n_in,
                              void* d_out, int out_size)
{
    const float* x    = (const float*)d_in[0];
    const float* e    = (const float*)d_in[1];
    const float* W_en = (const float*)d_in[2];
    const float* W_q  = (const float*)d_in[3];
    const float* W_o  = (const float*)d_in[4];
    float* out = (float*)d_out;

    float *qp, *kvp, *yp;
    cudaGetSymbolAddress((void**)&qp, g_q);
    cudaGetSymbolAddress((void**)&kvp, g_kv);
    cudaGetSymbolAddress((void**)&yp, g_y);

    // q = x @ W_q : [4096,1024] @ [1024,1024]
    {
        dim3 grid(DIM / 128, M_ROWS / 128);
        gemm_tc<<<grid, 256>>>(x, W_q, qp, M_ROWS, DIM, DIM);
    }
    // kv = e @ W_en : [4096,1024] @ [1024,2048]
    {
        dim3 grid((2 * DIM) / 128, M_ROWS / 128);
        gemm_tc<<<grid, 256>>>(e, W_en, kvp, M_ROWS, 2 * DIM, DIM);
    }
    // attention -> y
    {
        dim3 grid(SEQ / 64, BATCH * NHEAD);
        attn_tc<<<grid, 128>>>(qp, kvp, yp);
    }
    // out = y @ W_o : [4096,1024] @ [1024,1024]
    {
        dim3 grid(DIM / 128, M_ROWS / 128);
        gemm_tc<<<grid, 256>>>(yp, W_o, out, M_ROWS, DIM, DIM);
    }
}